// round 14
// baseline (speedup 1.0000x reference)
#include <cuda_runtime.h>
#include <cstdint>
#include <math_constants.h>

// Sparsemax along last dim (d = 1024), one warp per row, row in registers.
// Compute identical to the best kernel (R13): Michelot fixed-point from
// tau0 = max(z)-1 (valid: tau* >= max-1), actives binned into 3+3 regs/lane
// via two independent 16-deep chains, iterations via single-instruction
// integer redux.sync on 2^21 fixed-point sums. Rare overflow ->
// full-register float-shuffle fallback. No smem, no block barriers.
//
// CHANGE vs R13: __launch_bounds__(128, 10) caps regs at 51 (was 55) ->
// 10 blocks/SM = 40 warps (+11% resident warps). Only ~4 overhead regs to
// shave — payload untouched, so no spill risk like the hard 40-reg cap.
// Output pointer derived from a single (p - z) element delta to cut live
// bookkeeping registers.

constexpr int D   = 1024;
constexpr int WPB = 4;               // warps (rows) per block
constexpr int TPB = WPB * 32;        // 128 threads

#define FPSCALE     2097152.0f        // 2^21
#define FPSCALE_INV 4.76837158203125e-7f

// Order-preserving float<->int mapping (valid for non-NaN inputs).
__device__ __forceinline__ int f2i_mono(float f) {
    int i = __float_as_int(f);
    return i >= 0 ? i : i ^ 0x7fffffff;
}
__device__ __forceinline__ float i2f_mono(int i) {
    return __int_as_float(i >= 0 ? i : i ^ 0x7fffffff);
}

__device__ __forceinline__ float warp_sum(float x) {
#pragma unroll
    for (int o = 16; o > 0; o >>= 1)
        x += __shfl_xor_sync(0xffffffffu, x, o);
    return x;
}

__global__ void __launch_bounds__(TPB, 10)
sparsemax_kernel(const float* __restrict__ z, ptrdiff_t out_delta, int rows) {
    const int wl   = threadIdx.x >> 5;
    const int lane = threadIdx.x & 31;
    const int row  = blockIdx.x * WPB + wl;
    if (row >= rows) return;

    const float* zr = z + (size_t)row * D + lane * 4;

    // ---- load row: 8 x float4 per lane, coalesced, streaming ----
    float v[32];
#pragma unroll
    for (int j = 0; j < 8; j++) {
        float4 t = __ldcs(reinterpret_cast<const float4*>(zr + j * 128));
        v[4 * j + 0] = t.x;
        v[4 * j + 1] = t.y;
        v[4 * j + 2] = t.z;
        v[4 * j + 3] = t.w;
    }

    // ---- row max: register tree (ILP) + single-instruction int redux ----
    float m = v[0];
#pragma unroll
    for (int i = 1; i < 32; i++) m = fmaxf(m, v[i]);
    m = i2f_mono(__reduce_max_sync(0xffffffffu, f2i_mono(m)));

    float tau = m - 1.0f;

    // ---- bin actives {z > tau0}: two independent 16-deep chains, 3+3 slots ----
    float x0 = -CUDART_INF_F, x1 = -CUDART_INF_F, x2 = -CUDART_INF_F;
    float x3 = -CUDART_INF_F, x4 = -CUDART_INF_F, x5 = -CUDART_INF_F;
    int lc0 = 0, lc1 = 0;
#pragma unroll
    for (int i = 0; i < 16; i++) {
        if (v[i] > tau) {
            if (lc0 == 0)      x0 = v[i];
            else if (lc0 == 1) x1 = v[i];
            else if (lc0 == 2) x2 = v[i];
            lc0++;
        }
    }
#pragma unroll
    for (int i = 16; i < 32; i++) {
        if (v[i] > tau) {
            if (lc1 == 0)      x3 = v[i];
            else if (lc1 == 1) x4 = v[i];
            else if (lc1 == 2) x5 = v[i];
            lc1++;
        }
    }
    const bool overflow =
        __ballot_sync(0xffffffffu, (lc0 > 3) || (lc1 > 3)) != 0u;

    // ---- Michelot fixed-point iterations ----
    if (!overflow) {
        // common case: all actives in x0..x5 across the warp.
        // Sums via integer redux.sync on 2^21 fixed point (single instr).
#pragma unroll 1
        for (int it = 0; it < 40; it++) {
            bool a0 = x0 > tau, a1 = x1 > tau, a2 = x2 > tau;
            bool a3 = x3 > tau, a4 = x4 > tau, a5 = x5 > tau;
            float ls = ((a0 ? x0 : 0.0f) + (a1 ? x1 : 0.0f))
                     + ((a2 ? x2 : 0.0f) + (a3 ? x3 : 0.0f))
                     + ((a4 ? x4 : 0.0f) + (a5 ? x5 : 0.0f));
            int lk = (int)a0 + (int)a1 + (int)a2
                   + (int)a3 + (int)a4 + (int)a5;
            int S = __reduce_add_sync(0xffffffffu, __float2int_rn(ls * FPSCALE));
            int K = __reduce_add_sync(0xffffffffu, lk);      // K >= 1 always
            float nt = ((float)S * FPSCALE_INV - 1.0f) / (float)K;
            if (nt == tau) break;   // set stable -> fixed point reached
            tau = nt;
        }
    } else {
        // rare fallback: full register row, pure float shuffle reductions
#pragma unroll 1
        for (int it = 0; it < 64; it++) {
            float s = 0.0f, kk = 0.0f;
#pragma unroll
            for (int i = 0; i < 32; i++) {
                bool a = v[i] > tau;
                s  += a ? v[i] : 0.0f;
                kk += a ? 1.0f : 0.0f;
            }
            s  = warp_sum(s);
            kk = warp_sum(kk);
            float nt = (s - 1.0f) / kk;
            if (nt == tau) break;
            tau = nt;
        }
    }

    // ---- write p = relu(z - tau), coalesced float4 streaming stores ----
    float* pr = const_cast<float*>(zr) + out_delta;
#pragma unroll
    for (int j = 0; j < 8; j++) {
        float4 t;
        t.x = fmaxf(v[4 * j + 0] - tau, 0.0f);
        t.y = fmaxf(v[4 * j + 1] - tau, 0.0f);
        t.z = fmaxf(v[4 * j + 2] - tau, 0.0f);
        t.w = fmaxf(v[4 * j + 3] - tau, 0.0f);
        __stcs(reinterpret_cast<float4*>(pr + j * 128), t);
    }
}

extern "C" void kernel_launch(void* const* d_in, const int* in_sizes, int n_in,
                              void* d_out, int out_size) {
    const float* z = (const float*)d_in[0];
    float* p = (float*)d_out;
    const int rows = in_sizes[0] / D;                  // 32768
    const int grid = (rows + WPB - 1) / WPB;           // 8192
    const ptrdiff_t delta = p - z;                     // element delta
    sparsemax_kernel<<<grid, TPB>>>(z, delta, rows);
}